// round 6
// baseline (speedup 1.0000x reference)
#include <cuda_runtime.h>
#include <math.h>

#define NN 8192
#define EE 131072
#define CC 16
#define MID 16
#define KV 16
#define CKV 8
#define CO 8
#define SCALE 0.35355339059327373f   // 1/sqrt((ckv/HEADS)*4) = 1/sqrt(8)

// ---------------- scratch (static device globals; no runtime allocation) ----------------
__device__ float g_P0[NN * MID * KV];          // [n][h][o]
__device__ float g_P1[NN * MID * KV];          // [n][h][o]
__device__ float g_P2[NN * MID * 3 * KV];      // [n][h][q][o]
__device__ float g_P3[NN * MID * 9 * KV];      // [n][h][f][q][o]
__device__ float g_q0[NN * CKV];               // [n][d]
__device__ float g_q1[NN * CKV * 3];           // [n][d][m]
__device__ float g_v0[EE * CKV];               // [e][c]
__device__ float g_v1[EE * CKV * 3];           // [e][c][m]
__device__ float g_z[EE * 4];                  // [e][head]  (already scaled)
__device__ unsigned g_m[NN * 4];               // orderable-uint max per (n,head)
__device__ float g_s[NN * 4];                  // softmax denom
__device__ float g_o0[NN * CKV];               // attention out deg0
__device__ float g_o1[NN * CKV * 3];           // attention out deg1
__device__ float g_x0[NN * CC];                // current node features deg0
__device__ float g_x1[NN * CC * 3];            // current node features deg1

// float <-> orderable uint (for atomicMax on floats of any sign)
__device__ __forceinline__ unsigned f2o(float f) {
    unsigned u = __float_as_uint(f);
    return (u & 0x80000000u) ? ~u : (u | 0x80000000u);
}
__device__ __forceinline__ float o2f(unsigned u) {
    return (u & 0x80000000u) ? __uint_as_float(u ^ 0x80000000u) : __uint_as_float(~u);
}

// ---------------- init per-layer accumulators ----------------
__global__ void k_init() {
    int i = blockIdx.x * blockDim.x + threadIdx.x;
    if (i < NN * 4) { g_m[i] = 0x007fffffu; /* f2o(-inf) */ g_s[i] = 0.f; }
    if (i < NN * CKV) g_o0[i] = 0.f;
    if (i < NN * CKV * 3) g_o1[i] = 0.f;
}

// ---------------- per-node precompute: P tensors + q vectors ----------------
// wnf1: 3 slices of [MID][KVD][CC]; w11: [MID][KVD][CC][3]; wql: [2][CC][CKV] (or null)
__global__ void k_node_pre(const float* __restrict__ xin0, const float* __restrict__ xin1,
                           int use_g,
                           const float* __restrict__ wnf1, const float* __restrict__ w11,
                           const float* __restrict__ wql, int KVD) {
    __shared__ float sx0[CC];
    __shared__ float sx1[CC * 3];
    const float* x0 = use_g ? g_x0 : xin0;
    const float* x1 = use_g ? g_x1 : xin1;
    int n = blockIdx.x, t = threadIdx.x;
    if (t < CC) sx0[t] = x0[n * CC + t];
    if (t < CC * 3) sx1[t] = x1[n * CC * 3 + t];
    __syncthreads();

    const int tot0 = MID * KVD;
    const int slice = MID * KVD * CC;
    for (int idx = t; idx < tot0; idx += 256) {
        int h = idx / KVD, o = idx % KVD;
        const float* wa = wnf1 + (h * KVD + o) * CC;           // slice 0
        const float* wb = wnf1 + slice + (h * KVD + o) * CC;   // slice 1
        float a0 = 0.f, a1 = 0.f;
#pragma unroll
        for (int i = 0; i < CC; i++) { a0 += wa[i] * sx0[i]; a1 += wb[i] * sx0[i]; }
        g_P0[n * tot0 + idx] = a0;
        g_P1[n * tot0 + idx] = a1;
    }
    const int tot2 = MID * 3 * KVD;
    for (int idx = t; idx < tot2; idx += 256) {
        int h = idx / (3 * KVD); int r = idx % (3 * KVD);
        int q = r / KVD, o = r % KVD;
        const float* w = wnf1 + 2 * slice + (h * KVD + o) * CC; // slice 2
        float a = 0.f;
#pragma unroll
        for (int i = 0; i < CC; i++) a += w[i] * sx1[i * 3 + q];
        g_P2[n * tot2 + idx] = a;
    }
    const int tot3 = MID * 9 * KVD;
    for (int idx = t; idx < tot3; idx += 256) {
        int h = idx / (9 * KVD); int r = idx % (9 * KVD);
        int f = r / (3 * KVD); int r2 = r % (3 * KVD);
        int q = r2 / KVD, o = r2 % KVD;
        const float* w = w11 + (h * KVD + o) * CC * 3 + f;      // [h][o][i][f], i-stride 3
        float a = 0.f;
#pragma unroll
        for (int i = 0; i < CC; i++) a += w[i * 3] * sx1[i * 3 + q];
        g_P3[n * tot3 + idx] = a;
    }
    if (wql) {
        if (t < CKV) {
            float a = 0.f;
#pragma unroll
            for (int c = 0; c < CC; c++) a += sx0[c] * wql[c * CKV + t];
            g_q0[n * CKV + t] = a;
        } else if (t < CKV + CKV * 3) {
            int j = t - CKV; int d = j / 3, m = j % 3;
            float a = 0.f;
#pragma unroll
            for (int c = 0; c < CC; c++) a += sx1[c * 3 + m] * wql[CC * CKV + c * CKV + d];
            g_q1[n * 24 + j] = a;
        }
    }
}

// ---------------- edge pass A: H (inline), kv messages, z, v store, atomicMax ----------------
// 128 threads = 8 edges x 16 threads(o)
__global__ void k_edgeA(const float* __restrict__ ef, const float* __restrict__ w1l,
                        const float* __restrict__ b00, const float* __restrict__ b01,
                        const float* __restrict__ b10, const float* __restrict__ b11,
                        const int* __restrict__ esrc, const int* __restrict__ edst) {
    __shared__ float sH[8][64];
    __shared__ float sef[8][16];
    int e0 = blockIdx.x * 8;
    int t = threadIdx.x;
    { int le = t / 16, f = t % 16; sef[le][f] = ef[(e0 + le) * 16 + f]; }
    __syncthreads();
#pragma unroll
    for (int j = 0; j < 4; j++) {
        int idx = t + j * 128;                 // 0..511 = 8 edges x (p,h)
        int le = idx / 64, ph = idx % 64, p = ph / 16, h = ph % 16;
        const float* w = w1l + p * 256 + h;    // [p][f][h]
        float a = 0.f;
#pragma unroll
        for (int f = 0; f < 16; f++) a += sef[le][f] * w[f * 16];
        sH[le][ph] = fmaxf(a, 0.f);
    }
    __syncthreads();

    int le = t / 16, o = t % 16;
    int e = e0 + le;
    int src = esrc[e], dst = edst[e];
    const float* H = sH[le];
    const float* P0p = g_P0 + src * 256 + o;
    const float* P1p = g_P1 + src * 256 + o;
    const float* P2p = g_P2 + src * 768 + o;
    const float* P3p = g_P3 + src * 2304 + o;

    float a00 = 0.f, a01 = 0.f;
    float z2[3] = {0.f, 0.f, 0.f};
    float Z[9] = {0.f, 0.f, 0.f, 0.f, 0.f, 0.f, 0.f, 0.f, 0.f};
#pragma unroll
    for (int h = 0; h < 16; h++) {
        float h0 = H[h], h1 = H[16 + h], h2 = H[32 + h], h3 = H[48 + h];
        a00 += h0 * P0p[h * 16];
        a01 += h1 * P1p[h * 16];
#pragma unroll
        for (int q = 0; q < 3; q++) z2[q] += h2 * P2p[h * 48 + q * 16];
#pragma unroll
        for (int fq = 0; fq < 9; fq++) Z[fq] += h3 * P3p[h * 144 + fq * 16];
    }
    float kv0 = b00[e] * a00;
#pragma unroll
    for (int q = 0; q < 3; q++) kv0 += b10[e * 3 + q] * z2[q];
    float kv1[3];
#pragma unroll
    for (int p = 0; p < 3; p++) {
        float acc = b01[e * 3 + p] * a01;
#pragma unroll
        for (int q = 0; q < 3; q++)
#pragma unroll
            for (int f = 0; f < 3; f++)
                acc += b11[e * 27 + p * 9 + q * 3 + f] * Z[f * 3 + q];
        kv1[p] = acc;
    }

    float zpart = 0.f;
    if (o < 8) {
        zpart = g_q0[dst * 8 + o] * kv0;
#pragma unroll
        for (int p = 0; p < 3; p++) zpart += g_q1[dst * 24 + o * 3 + p] * kv1[p];
    }
    float zsum = zpart + __shfl_xor_sync(0xffffffffu, zpart, 1);
    if (o < 8 && (o & 1) == 0) {
        int head = o >> 1;
        float zs = zsum * SCALE;
        g_z[e * 4 + head] = zs;
        atomicMax(&g_m[dst * 4 + head], f2o(zs));
    }
    if (o >= 8) {
        int c = o - 8;
        g_v0[e * 8 + c] = kv0;
        g_v1[(e * 8 + c) * 3 + 0] = kv1[0];
        g_v1[(e * 8 + c) * 3 + 1] = kv1[1];
        g_v1[(e * 8 + c) * 3 + 2] = kv1[2];
    }
}

// ---------------- edge pass B: exp-sum ----------------
__global__ void k_edgeB(const int* __restrict__ edst) {
    int i = blockIdx.x * 256 + threadIdx.x;   // E*4
    if (i >= EE * 4) return;
    int e = i >> 2, head = i & 3;
    int dst = edst[e];
    float m = o2f(g_m[dst * 4 + head]);
    float ez = __expf(g_z[i] - m);
    atomicAdd(&g_s[dst * 4 + head], ez);
}

// ---------------- edge pass C: alpha * v scatter ----------------
__global__ void k_edgeC(const int* __restrict__ edst) {
    int i = blockIdx.x * 256 + threadIdx.x;   // E*8
    if (i >= EE * 8) return;
    int e = i >> 3, c = i & 7, head = c >> 1;
    int dst = edst[e];
    float m = o2f(g_m[dst * 4 + head]);
    float s = g_s[dst * 4 + head];
    float alpha = __expf(g_z[e * 4 + head] - m) / (s + 1e-9f);
    atomicAdd(&g_o0[dst * 8 + c], alpha * g_v0[i]);
    float* o1p = g_o1 + (dst * 8 + c) * 3;
    const float* v1p = g_v1 + i * 3;
    atomicAdd(o1p + 0, alpha * v1p[0]);
    atomicAdd(o1p + 1, alpha * v1p[1]);
    atomicAdd(o1p + 2, alpha * v1p[2]);
}

// ---------------- node pass D: projection + SE3 norm ----------------
// 256 threads = 16 nodes x 16 channels
__global__ void k_nodeD(const float* __restrict__ xin0, const float* __restrict__ xin1,
                        int use_g,
                        const float* __restrict__ wp, const float* __restrict__ gamma,
                        const float* __restrict__ beta) {
    __shared__ float s0[16][24];
    __shared__ float s1[16][72];
    const float* x0 = use_g ? g_x0 : xin0;
    const float* x1 = use_g ? g_x1 : xin1;
    int n0b = blockIdx.x * 16;
    int t = threadIdx.x;
    for (int idx = t; idx < 16 * 24; idx += 256) {
        int nl = idx / 24, c = idx % 24; int n = n0b + nl;
        s0[nl][c] = (c < 8) ? g_o0[n * 8 + c] : x0[n * 16 + (c - 8)];
    }
    for (int idx = t; idx < 16 * 72; idx += 256) {
        int nl = idx / 72, r = idx % 72; int c = r / 3, m = r % 3; int n = n0b + nl;
        s1[nl][r] = (c < 8) ? g_o1[n * 24 + c * 3 + m] : x1[n * 48 + (c - 8) * 3 + m];
    }
    __syncthreads();

    int nl = t / 16, d = t % 16; int n = n0b + nl;
    float y0 = 0.f, y1[3] = {0.f, 0.f, 0.f};
#pragma unroll
    for (int c = 0; c < 24; c++) {
        y0 += s0[nl][c] * wp[c * 16 + d];
        float w = wp[384 + c * 16 + d];
        y1[0] += s1[nl][c * 3 + 0] * w;
        y1[1] += s1[nl][c * 3 + 1] * w;
        y1[2] += s1[nl][c * 3 + 2] * w;
    }
    // ---- norm deg0 ----
    {
        float nv = sqrtf(y0 * y0 + 1e-12f);
        float r = nv;
#pragma unroll
        for (int mk = 1; mk < 16; mk <<= 1) r += __shfl_xor_sync(0xffffffffu, r, mk);
        float mu = r * (1.f / 16.f);
        float dv = nv - mu;
        float v = dv * dv;
#pragma unroll
        for (int mk = 1; mk < 16; mk <<= 1) v += __shfl_xor_sync(0xffffffffu, v, mk);
        v *= (1.f / 16.f);
        float ln = dv * rsqrtf(v + 1e-5f) * gamma[d] + beta[d];
        float fac = fmaxf(ln, 0.f) / (nv + 1e-3f);
        g_x0[n * 16 + d] = y0 * fac;
    }
    // ---- norm deg1 ----
    {
        float nv = sqrtf(y1[0] * y1[0] + y1[1] * y1[1] + y1[2] * y1[2] + 1e-12f);
        float r = nv;
#pragma unroll
        for (int mk = 1; mk < 16; mk <<= 1) r += __shfl_xor_sync(0xffffffffu, r, mk);
        float mu = r * (1.f / 16.f);
        float dv = nv - mu;
        float v = dv * dv;
#pragma unroll
        for (int mk = 1; mk < 16; mk <<= 1) v += __shfl_xor_sync(0xffffffffu, v, mk);
        v *= (1.f / 16.f);
        float ln = dv * rsqrtf(v + 1e-5f) * gamma[16 + d] + beta[16 + d];
        float fac = fmaxf(ln, 0.f) / (nv + 1e-3f);
        g_x1[n * 48 + d * 3 + 0] = y1[0] * fac;
        g_x1[n * 48 + d * 3 + 1] = y1[1] * fac;
        g_x1[n * 48 + d * 3 + 2] = y1[2] * fac;
    }
}

// ---------------- final: init output with self term ----------------
__global__ void k_initout(const float* __restrict__ wself, float* __restrict__ out) {
    int i = blockIdx.x * 256 + threadIdx.x;   // N*32
    if (i >= NN * 32) return;
    int n = i >> 5, j = i & 31;
    float a = 0.f;
    if (j < 8) {
#pragma unroll
        for (int c = 0; c < 16; c++) a += g_x0[n * 16 + c] * wself[c * 8 + j];
    } else {
        int r = j - 8; int o = r / 3, m = r % 3;
#pragma unroll
        for (int c = 0; c < 16; c++) a += g_x1[n * 48 + c * 3 + m] * wself[128 + c * 8 + o];
    }
    out[i] = a;
}

// ---------------- final: fc edge messages, scatter into out ----------------
// 128 threads = 16 edges x 8 threads(o)
__global__ void k_edge_fc(const float* __restrict__ ef, const float* __restrict__ w1l,
                          const float* __restrict__ b00, const float* __restrict__ b01,
                          const float* __restrict__ b10, const float* __restrict__ b11,
                          const int* __restrict__ esrc, const int* __restrict__ edst,
                          float* __restrict__ out) {
    __shared__ float sH[16][64];
    __shared__ float sef[16][16];
    int e0 = blockIdx.x * 16;
    int t = threadIdx.x;
    for (int idx = t; idx < 16 * 16; idx += 128)
        sef[idx / 16][idx % 16] = ef[(e0 + idx / 16) * 16 + idx % 16];
    __syncthreads();
#pragma unroll
    for (int j = 0; j < 8; j++) {
        int idx = t + j * 128;                 // 0..1023 = 16 edges x (p,h)
        int le = idx / 64, ph = idx % 64, p = ph / 16, h = ph % 16;
        const float* w = w1l + p * 256 + h;
        float a = 0.f;
#pragma unroll
        for (int f = 0; f < 16; f++) a += sef[le][f] * w[f * 16];
        sH[le][ph] = fmaxf(a, 0.f);
    }
    __syncthreads();

    int le = t / 8, o = t % 8;
    int e = e0 + le;
    int src = esrc[e], dst = edst[e];
    const float* H = sH[le];
    const float* P0p = g_P0 + src * 128 + o;
    const float* P1p = g_P1 + src * 128 + o;
    const float* P2p = g_P2 + src * 384 + o;
    const float* P3p = g_P3 + src * 1152 + o;

    float a00 = 0.f, a01 = 0.f;
    float z2[3] = {0.f, 0.f, 0.f};
    float Z[9] = {0.f, 0.f, 0.f, 0.f, 0.f, 0.f, 0.f, 0.f, 0.f};
#pragma unroll
    for (int h = 0; h < 16; h++) {
        float h0 = H[h], h1 = H[16 + h], h2 = H[32 + h], h3 = H[48 + h];
        a00 += h0 * P0p[h * 8];
        a01 += h1 * P1p[h * 8];
#pragma unroll
        for (int q = 0; q < 3; q++) z2[q] += h2 * P2p[h * 24 + q * 8];
#pragma unroll
        for (int fq = 0; fq < 9; fq++) Z[fq] += h3 * P3p[h * 72 + fq * 8];
    }
    float m0 = b00[e] * a00;
#pragma unroll
    for (int q = 0; q < 3; q++) m0 += b10[e * 3 + q] * z2[q];
    atomicAdd(&out[dst * 32 + o], m0);
#pragma unroll
    for (int p = 0; p < 3; p++) {
        float acc = b01[e * 3 + p] * a01;
#pragma unroll
        for (int q = 0; q < 3; q++)
#pragma unroll
            for (int f = 0; f < 3; f++)
                acc += b11[e * 27 + p * 9 + q * 3 + f] * Z[f * 3 + q];
        atomicAdd(&out[dst * 32 + 8 + o * 3 + p], acc);
    }
}

// ---------------- host orchestration ----------------
extern "C" void kernel_launch(void* const* d_in, const int* in_sizes, int n_in,
                              void* d_out, int out_size) {
    const float* x0       = (const float*)d_in[0];
    const float* x1       = (const float*)d_in[1];
    const float* ef       = (const float*)d_in[2];
    const float* b00      = (const float*)d_in[3];
    const float* b01      = (const float*)d_in[4];
    const float* b10      = (const float*)d_in[5];
    const float* b11      = (const float*)d_in[6];
    const float* kv_w1    = (const float*)d_in[7];
    const float* kv_wnf1  = (const float*)d_in[8];
    const float* kv_w11   = (const float*)d_in[9];
    const float* wq       = (const float*)d_in[10];
    const float* wproj    = (const float*)d_in[11];
    const float* gam      = (const float*)d_in[12];
    const float* bet      = (const float*)d_in[13];
    const float* fc_w1    = (const float*)d_in[14];
    const float* fc_wnf1  = (const float*)d_in[15];
    const float* fc_w11   = (const float*)d_in[16];
    const float* fc_wself = (const float*)d_in[17];
    const int*   esrc     = (const int*)d_in[18];
    const int*   edst     = (const int*)d_in[19];
    float* out = (float*)d_out;

    for (int l = 0; l < 2; l++) {
        int use_g = (l != 0);
        k_init<<<(NN * 24 + 255) / 256, 256>>>();
        k_node_pre<<<NN, 256>>>(x0, x1, use_g,
                                kv_wnf1 + l * 3 * MID * KV * CC,
                                kv_w11  + l * MID * KV * CC * 3,
                                wq + l * 2 * CC * CKV, KV);
        k_edgeA<<<EE / 8, 128>>>(ef, kv_w1 + l * 4 * 16 * 16, b00, b01, b10, b11, esrc, edst);
        k_edgeB<<<(EE * 4) / 256, 256>>>(edst);
        k_edgeC<<<(EE * 8) / 256, 256>>>(edst);
        k_nodeD<<<NN / 16, 256>>>(x0, x1, use_g, wproj + l * 768, gam + l * 32, bet + l * 32);
    }
    // final fc pass
    k_node_pre<<<NN, 256>>>(nullptr, nullptr, 1, fc_wnf1, fc_w11, nullptr, CO);
    k_initout<<<(NN * 32) / 256, 256>>>(fc_wself, out);
    k_edge_fc<<<EE / 16, 128>>>(ef, fc_w1, b00, b01, b10, b11, esrc, edst, out);
}

// round 9
// speedup vs baseline: 2.1048x; 2.1048x over previous
#include <cuda_runtime.h>
#include <math.h>

#define NN 8192
#define EE 131072
#define CC 16
#define MID 16
#define KV 16
#define CKV 8
#define CO 8
#define SCALE 0.35355339059327373f   // 1/sqrt((ckv/HEADS)*4) = 1/sqrt(8)

// ---------------- scratch (static device globals) ----------------
__device__ float g_P0[NN * MID * KV];          // [n][h][o]
__device__ float g_P1[NN * MID * KV];          // [n][h][o]
__device__ float g_P2[NN * MID * 3 * KV];      // [n][h][q][o]
__device__ float g_P3[NN * MID * 9 * KV];      // [n][h][f][q][o]
__device__ float g_q0[NN * CKV];               // [n][d]
__device__ float g_q1[NN * CKV * 3];           // [n][d][m]
__device__ float g_v0[EE * CKV];               // [e][c]
__device__ float g_v1[EE * CKV * 3];           // [e][c][m]
__device__ float g_z[EE * 4];                  // [e][head]  (scaled)
__device__ unsigned g_m[NN * 4];               // orderable-uint max per (n,head)
__device__ float g_s[NN * 4];                  // softmax denom
__device__ float g_o0[NN * CKV];
__device__ float g_o1[NN * CKV * 3];
__device__ float g_x0[NN * CC];
__device__ float g_x1[NN * CC * 3];
// CSR by src
__device__ int g_deg[NN];
__device__ int g_cur[NN];
__device__ int g_rs[NN + 1];
__device__ int g_eperm[EE];

__device__ __forceinline__ unsigned f2o(float f) {
    unsigned u = __float_as_uint(f);
    return (u & 0x80000000u) ? ~u : (u | 0x80000000u);
}
__device__ __forceinline__ float o2f(unsigned u) {
    return (u & 0x80000000u) ? __uint_as_float(u ^ 0x80000000u) : __uint_as_float(~u);
}

// ---------------- CSR build ----------------
__global__ void k_csr_zero() {
    int i = blockIdx.x * 256 + threadIdx.x;
    if (i < NN) { g_deg[i] = 0; g_cur[i] = 0; }
}
__global__ void k_csr_count(const int* __restrict__ esrc) {
    int e = blockIdx.x * 256 + threadIdx.x;
    if (e < EE) atomicAdd(&g_deg[esrc[e]], 1);
}
__global__ void k_csr_scan() {     // 1 block, 1024 threads, 8 elems each
    __shared__ int tot[1024];
    int t = threadIdx.x;
    int base = t * 8;
    int loc[8];
    int s = 0;
#pragma unroll
    for (int i = 0; i < 8; i++) { loc[i] = s; s += g_deg[base + i]; }
    tot[t] = s;
    __syncthreads();
    for (int off = 1; off < 1024; off <<= 1) {
        int v = (t >= off) ? tot[t - off] : 0;
        __syncthreads();
        tot[t] += v;
        __syncthreads();
    }
    int excl = (t == 0) ? 0 : tot[t - 1];
#pragma unroll
    for (int i = 0; i < 8; i++) g_rs[base + i] = excl + loc[i];
    if (t == 0) g_rs[NN] = EE;
}
__global__ void k_csr_fill(const int* __restrict__ esrc) {
    int e = blockIdx.x * 256 + threadIdx.x;
    if (e < EE) {
        int s = esrc[e];
        int pos = g_rs[s] + atomicAdd(&g_cur[s], 1);
        g_eperm[pos] = e;
    }
}

// ---------------- init per-layer accumulators ----------------
__global__ void k_init() {
    int i = blockIdx.x * blockDim.x + threadIdx.x;
    if (i < NN * 4) { g_m[i] = 0x007fffffu; g_s[i] = 0.f; }
    if (i < NN * CKV) g_o0[i] = 0.f;
    if (i < NN * CKV * 3) g_o1[i] = 0.f;
}

// ---------------- node precompute: GEMM-style, weight chunks in SMEM ----------------
// 32 nodes/block, chunks of 128 output-rows. Unified j index over [0, 224*KVD):
//  [0,16K): P0 (x0)  [16K,32K): P1 (x0)  [32K,80K): P2 (x1,q)  [80K,224K): P3 (x1,q)
template<int KVD>
__global__ void k_node_pre2(const float* __restrict__ xin0, const float* __restrict__ xin1,
                            int use_g,
                            const float* __restrict__ wnf1, const float* __restrict__ w11) {
    __shared__ float sx0[32][16];
    __shared__ float sx1[32][48];
    __shared__ float wch[128][17];
    const float* x0 = use_g ? g_x0 : xin0;
    const float* x1 = use_g ? g_x1 : xin1;
    int nb = blockIdx.x * 32;
    int t = threadIdx.x;
    for (int idx = t; idx < 32 * 16; idx += 256) sx0[idx >> 4][idx & 15] = x0[nb * 16 + idx];
    for (int idx = t; idx < 32 * 48; idx += 256) sx1[idx / 48][idx % 48] = x1[nb * 48 + idx];

    const int slice = 16 * KVD * 16;
    const int JT = 224 * KVD;
    for (int jc = 0; jc < JT; jc += 128) {
        __syncthreads();
        // load 128x16 weight chunk
#pragma unroll
        for (int k = 0; k < 8; k++) {
            int item = t + k * 256;
            int jl = item >> 4, i = item & 15;
            int j = jc + jl;
            float w;
            if (j < 32 * KVD) {
                w = wnf1[j * 16 + i];                                    // slices 0,1 contiguous
            } else if (j < 80 * KVD) {
                int r = j - 32 * KVD;
                int h = r / (3 * KVD);
                int o = r % KVD;
                w = wnf1[2 * slice + (h * KVD + o) * 16 + i];
            } else {
                int r = j - 80 * KVD;
                int h = r / (9 * KVD);
                int rem = r % (9 * KVD);
                int f = rem / (3 * KVD);
                int o = rem % KVD;
                w = w11[((h * KVD + o) * 16 + i) * 3 + f];
            }
            wch[jl][i] = w;
        }
        __syncthreads();
        // 32 nodes x 128 j = 4096 items, 16/thread; writes coalesced in j
#pragma unroll
        for (int k = 0; k < 16; k++) {
            int item = t + k * 256;
            int nl = item >> 7;
            int jl = item & 127;
            int j = jc + jl;
            int n = nb + nl;
            const float* w = wch[jl];
            float a = 0.f;
            if (j < 32 * KVD) {
                const float* xs = sx0[nl];
#pragma unroll
                for (int i = 0; i < 16; i++) a += w[i] * xs[i];
                if (j < 16 * KVD) g_P0[n * (16 * KVD) + j] = a;
                else              g_P1[n * (16 * KVD) + (j - 16 * KVD)] = a;
            } else if (j < 80 * KVD) {
                int r = j - 32 * KVD;
                int q = (r % (3 * KVD)) / KVD;
                const float* xs = &sx1[nl][q];
#pragma unroll
                for (int i = 0; i < 16; i++) a += w[i] * xs[i * 3];
                g_P2[n * (48 * KVD) + r] = a;
            } else {
                int r = j - 80 * KVD;
                int q = (r % (3 * KVD)) / KVD;
                const float* xs = &sx1[nl][q];
#pragma unroll
                for (int i = 0; i < 16; i++) a += w[i] * xs[i * 3];
                g_P3[n * (144 * KVD) + r] = a;
            }
        }
    }
}

// ---------------- q vectors ----------------
__global__ void k_q(const float* __restrict__ xin0, const float* __restrict__ xin1,
                    int use_g, const float* __restrict__ wql) {
    const float* x0 = use_g ? g_x0 : xin0;
    const float* x1 = use_g ? g_x1 : xin1;
    int i = blockIdx.x * 256 + threadIdx.x;   // NN*32
    if (i >= NN * 32) return;
    int n = i >> 5, j = i & 31;
    if (j < 8) {
        float a = 0.f;
#pragma unroll
        for (int c = 0; c < 16; c++) a += x0[n * 16 + c] * wql[c * 8 + j];
        g_q0[n * 8 + j] = a;
    } else {
        int r = j - 8; int d = r / 3, m = r % 3;
        float a = 0.f;
#pragma unroll
        for (int c = 0; c < 16; c++) a += x1[n * 48 + c * 3 + m] * wql[128 + c * 8 + d];
        g_q1[n * 24 + r] = a;
    }
}

// ---------------- edge pass A (CSR): block per src node, P in SMEM ----------------
// 256 threads = 16 edges x 16 threads(o) per chunk
__global__ void k_edgeA2(const float* __restrict__ ef, const float* __restrict__ w1l,
                         const float* __restrict__ b00, const float* __restrict__ b01,
                         const float* __restrict__ b10, const float* __restrict__ b11,
                         const int* __restrict__ edst) {
    __shared__ float sP0[256], sP1[256], sP2[768], sP3[2304];
    __shared__ float sw1[1024];
    __shared__ float sH[16][64];
    __shared__ float sef[16][16];
    __shared__ float sB[16][34];
    __shared__ float sq[16][32];
    __shared__ int se[16], sdst[16];
    int n = blockIdx.x;
    int start = g_rs[n], end = g_rs[n + 1];
    if (start == end) return;
    int t = threadIdx.x;
    sP0[t] = g_P0[n * 256 + t];
    sP1[t] = g_P1[n * 256 + t];
    for (int i = t; i < 768; i += 256) sP2[i] = g_P2[n * 768 + i];
    for (int i = t; i < 2304; i += 256) sP3[i] = g_P3[n * 2304 + i];
    for (int i = t; i < 1024; i += 256) sw1[i] = w1l[i];

    for (int c = start; c < end; c += 16) {
        int ne = min(16, end - c);
        __syncthreads();                          // smem reuse fence (also orders sP/sw1 loads)
        if (t < 16) {
            int e = (t < ne) ? g_eperm[c + t] : g_eperm[c];
            se[t] = e;
            sdst[t] = edst[e];
        }
        __syncthreads();
        { int le = t >> 4, f = t & 15; if (le < ne) sef[le][f] = ef[se[le] * 16 + f]; }
        for (int idx = t; idx < 16 * 34; idx += 256) {
            int le = idx / 34, j = idx % 34;
            if (le < ne) {
                int e = se[le];
                float v;
                if (j == 0)      v = b00[e];
                else if (j < 4)  v = b10[e * 3 + j - 1];
                else if (j < 7)  v = b01[e * 3 + j - 4];
                else             v = b11[e * 27 + j - 7];
                sB[le][j] = v;
            }
        }
        for (int idx = t; idx < 16 * 32; idx += 256) {
            int le = idx >> 5, j = idx & 31;
            if (le < ne) {
                int dst = sdst[le];
                sq[le][j] = (j < 8) ? g_q0[dst * 8 + j] : g_q1[dst * 24 + (j - 8)];
            }
        }
        __syncthreads();
#pragma unroll
        for (int k = 0; k < 4; k++) {
            int idx = t + k * 256;
            int le = idx >> 6, ph = idx & 63, p = ph >> 4, h = ph & 15;
            if (le < ne) {
                float a = 0.f;
#pragma unroll
                for (int f = 0; f < 16; f++) a += sef[le][f] * sw1[p * 256 + f * 16 + h];
                sH[le][ph] = fmaxf(a, 0.f);
            }
        }
        __syncthreads();
        // message compute (unguarded reads from smem; stores guarded)
        int le = t >> 4, o = t & 15;
        const float* H = sH[le];
        float a00 = 0.f, a01 = 0.f;
        float z2[3] = {0.f, 0.f, 0.f};
        float Z[9] = {0.f, 0.f, 0.f, 0.f, 0.f, 0.f, 0.f, 0.f, 0.f};
#pragma unroll
        for (int h = 0; h < 16; h++) {
            float h0 = H[h], h1 = H[16 + h], h2 = H[32 + h], h3 = H[48 + h];
            a00 += h0 * sP0[h * 16 + o];
            a01 += h1 * sP1[h * 16 + o];
#pragma unroll
            for (int q = 0; q < 3; q++) z2[q] += h2 * sP2[h * 48 + q * 16 + o];
#pragma unroll
            for (int fq = 0; fq < 9; fq++) Z[fq] += h3 * sP3[h * 144 + fq * 16 + o];
        }
        const float* B = sB[le];
        float kv0 = B[0] * a00;
#pragma unroll
        for (int q = 0; q < 3; q++) kv0 += B[1 + q] * z2[q];
        float kv1[3];
#pragma unroll
        for (int p = 0; p < 3; p++) {
            float acc = B[4 + p] * a01;
#pragma unroll
            for (int q = 0; q < 3; q++)
#pragma unroll
                for (int f = 0; f < 3; f++)
                    acc += B[7 + p * 9 + q * 3 + f] * Z[f * 3 + q];
            kv1[p] = acc;
        }
        float zpart = 0.f;
        if (o < 8) {
            zpart = sq[le][o] * kv0;
#pragma unroll
            for (int p = 0; p < 3; p++) zpart += sq[le][8 + o * 3 + p] * kv1[p];
        }
        float zsum = zpart + __shfl_xor_sync(0xffffffffu, zpart, 1);
        if (le < ne) {
            int e = se[le], dst = sdst[le];
            if (o < 8 && (o & 1) == 0) {
                int head = o >> 1;
                float zs = zsum * SCALE;
                g_z[e * 4 + head] = zs;
                atomicMax(&g_m[dst * 4 + head], f2o(zs));
            }
            if (o >= 8) {
                int cc = o - 8;
                g_v0[e * 8 + cc] = kv0;
                g_v1[(e * 8 + cc) * 3 + 0] = kv1[0];
                g_v1[(e * 8 + cc) * 3 + 1] = kv1[1];
                g_v1[(e * 8 + cc) * 3 + 2] = kv1[2];
            }
        }
    }
}

// ---------------- edge pass B: exp-sum ----------------
__global__ void k_edgeB(const int* __restrict__ edst) {
    int i = blockIdx.x * 256 + threadIdx.x;   // E*4
    if (i >= EE * 4) return;
    int e = i >> 2, head = i & 3;
    int dst = edst[e];
    float m = o2f(g_m[dst * 4 + head]);
    float ez = __expf(g_z[i] - m);
    atomicAdd(&g_s[dst * 4 + head], ez);
}

// ---------------- edge pass C: alpha * v scatter ----------------
__global__ void k_edgeC(const int* __restrict__ edst) {
    int i = blockIdx.x * 256 + threadIdx.x;   // E*8
    if (i >= EE * 8) return;
    int e = i >> 3, c = i & 7, head = c >> 1;
    int dst = edst[e];
    float m = o2f(g_m[dst * 4 + head]);
    float s = g_s[dst * 4 + head];
    float alpha = __expf(g_z[e * 4 + head] - m) / (s + 1e-9f);
    atomicAdd(&g_o0[dst * 8 + c], alpha * g_v0[i]);
    float* o1p = g_o1 + (dst * 8 + c) * 3;
    const float* v1p = g_v1 + i * 3;
    atomicAdd(o1p + 0, alpha * v1p[0]);
    atomicAdd(o1p + 1, alpha * v1p[1]);
    atomicAdd(o1p + 2, alpha * v1p[2]);
}

// ---------------- node pass D: projection + SE3 norm ----------------
__global__ void k_nodeD(const float* __restrict__ xin0, const float* __restrict__ xin1,
                        int use_g,
                        const float* __restrict__ wp, const float* __restrict__ gamma,
                        const float* __restrict__ beta) {
    __shared__ float s0[16][24];
    __shared__ float s1[16][72];
    const float* x0 = use_g ? g_x0 : xin0;
    const float* x1 = use_g ? g_x1 : xin1;
    int n0b = blockIdx.x * 16;
    int t = threadIdx.x;
    for (int idx = t; idx < 16 * 24; idx += 256) {
        int nl = idx / 24, c = idx % 24; int n = n0b + nl;
        s0[nl][c] = (c < 8) ? g_o0[n * 8 + c] : x0[n * 16 + (c - 8)];
    }
    for (int idx = t; idx < 16 * 72; idx += 256) {
        int nl = idx / 72, r = idx % 72; int c = r / 3, m = r % 3; int n = n0b + nl;
        s1[nl][r] = (c < 8) ? g_o1[n * 24 + c * 3 + m] : x1[n * 48 + (c - 8) * 3 + m];
    }
    __syncthreads();

    int nl = t / 16, d = t % 16; int n = n0b + nl;
    float y0 = 0.f, y1[3] = {0.f, 0.f, 0.f};
#pragma unroll
    for (int c = 0; c < 24; c++) {
        y0 += s0[nl][c] * wp[c * 16 + d];
        float w = wp[384 + c * 16 + d];
        y1[0] += s1[nl][c * 3 + 0] * w;
        y1[1] += s1[nl][c * 3 + 1] * w;
        y1[2] += s1[nl][c * 3 + 2] * w;
    }
    {
        float nv = sqrtf(y0 * y0 + 1e-12f);
        float r = nv;
#pragma unroll
        for (int mk = 1; mk < 16; mk <<= 1) r += __shfl_xor_sync(0xffffffffu, r, mk);
        float mu = r * (1.f / 16.f);
        float dv = nv - mu;
        float v = dv * dv;
#pragma unroll
        for (int mk = 1; mk < 16; mk <<= 1) v += __shfl_xor_sync(0xffffffffu, v, mk);
        v *= (1.f / 16.f);
        float ln = dv * rsqrtf(v + 1e-5f) * gamma[d] + beta[d];
        float fac = fmaxf(ln, 0.f) / (nv + 1e-3f);
        g_x0[n * 16 + d] = y0 * fac;
    }
    {
        float nv = sqrtf(y1[0] * y1[0] + y1[1] * y1[1] + y1[2] * y1[2] + 1e-12f);
        float r = nv;
#pragma unroll
        for (int mk = 1; mk < 16; mk <<= 1) r += __shfl_xor_sync(0xffffffffu, r, mk);
        float mu = r * (1.f / 16.f);
        float dv = nv - mu;
        float v = dv * dv;
#pragma unroll
        for (int mk = 1; mk < 16; mk <<= 1) v += __shfl_xor_sync(0xffffffffu, v, mk);
        v *= (1.f / 16.f);
        float ln = dv * rsqrtf(v + 1e-5f) * gamma[16 + d] + beta[16 + d];
        float fac = fmaxf(ln, 0.f) / (nv + 1e-3f);
        g_x1[n * 48 + d * 3 + 0] = y1[0] * fac;
        g_x1[n * 48 + d * 3 + 1] = y1[1] * fac;
        g_x1[n * 48 + d * 3 + 2] = y1[2] * fac;
    }
}

// ---------------- final: init output with self term ----------------
__global__ void k_initout(const float* __restrict__ wself, float* __restrict__ out) {
    int i = blockIdx.x * 256 + threadIdx.x;   // N*32
    if (i >= NN * 32) return;
    int n = i >> 5, j = i & 31;
    float a = 0.f;
    if (j < 8) {
#pragma unroll
        for (int c = 0; c < 16; c++) a += g_x0[n * 16 + c] * wself[c * 8 + j];
    } else {
        int r = j - 8; int o = r / 3, m = r % 3;
#pragma unroll
        for (int c = 0; c < 16; c++) a += g_x1[n * 48 + c * 3 + m] * wself[128 + c * 8 + o];
    }
    out[i] = a;
}

// ---------------- final fc pass (CSR): 32 edges x 8 threads(o) ----------------
__global__ void k_edge_fc2(const float* __restrict__ ef, const float* __restrict__ w1l,
                           const float* __restrict__ b00, const float* __restrict__ b01,
                           const float* __restrict__ b10, const float* __restrict__ b11,
                           const int* __restrict__ edst, float* __restrict__ out) {
    __shared__ float sP0[128], sP1[128], sP2[384], sP3[1152];
    __shared__ float sw1[1024];
    __shared__ float sH[32][64];
    __shared__ float sef[32][16];
    __shared__ float sB[32][34];
    __shared__ int se[32], sdst[32];
    int n = blockIdx.x;
    int start = g_rs[n], end = g_rs[n + 1];
    if (start == end) return;
    int t = threadIdx.x;
    if (t < 128) { sP0[t] = g_P0[n * 128 + t]; sP1[t] = g_P1[n * 128 + t]; }
    for (int i = t; i < 384; i += 256) sP2[i] = g_P2[n * 384 + i];
    for (int i = t; i < 1152; i += 256) sP3[i] = g_P3[n * 1152 + i];
    for (int i = t; i < 1024; i += 256) sw1[i] = w1l[i];

    for (int c = start; c < end; c += 32) {
        int ne = min(32, end - c);
        __syncthreads();
        if (t < 32) {
            int e = (t < ne) ? g_eperm[c + t] : g_eperm[c];
            se[t] = e;
            sdst[t] = edst[e];
        }
        __syncthreads();
        for (int idx = t; idx < 32 * 16; idx += 256) {
            int le = idx >> 4, f = idx & 15;
            if (le < ne) sef[le][f] = ef[se[le] * 16 + f];
        }
        for (int idx = t; idx < 32 * 34; idx += 256) {
            int le = idx / 34, j = idx % 34;
            if (le < ne) {
                int e = se[le];
                float v;
                if (j == 0)      v = b00[e];
                else if (j < 4)  v = b10[e * 3 + j - 1];
                else if (j < 7)  v = b01[e * 3 + j - 4];
                else             v = b11[e * 27 + j - 7];
                sB[le][j] = v;
            }
        }
        __syncthreads();
#pragma unroll
        for (int k = 0; k < 8; k++) {
            int idx = t + k * 256;
            int le = idx >> 6, ph = idx & 63, p = ph >> 4, h = ph & 15;
            if (le < ne) {
                float a = 0.f;
#pragma unroll
                for (int f = 0; f < 16; f++) a += sef[le][f] * sw1[p * 256 + f * 16 + h];
                sH[le][ph] = fmaxf(a, 0.f);
            }
        }
        __syncthreads();
        int le = t >> 3, o = t & 7;
        if (le < ne) {
            const float* H = sH[le];
            float a00 = 0.f, a01 = 0.f;
            float z2[3] = {0.f, 0.f, 0.f};
            float Z[9] = {0.f, 0.f, 0.f, 0.f, 0.f, 0.f, 0.f, 0.f, 0.f};
#pragma unroll
            for (int h = 0; h < 16; h++) {
                float h0 = H[h], h1 = H[16 + h], h2 = H[32 + h], h3 = H[48 + h];
                a00 += h0 * sP0[h * 8 + o];
                a01 += h1 * sP1[h * 8 + o];
#pragma unroll
                for (int q = 0; q < 3; q++) z2[q] += h2 * sP2[h * 24 + q * 8 + o];
#pragma unroll
                for (int fq = 0; fq < 9; fq++) Z[fq] += h3 * sP3[h * 72 + fq * 8 + o];
            }
            const float* B = sB[le];
            int dst = sdst[le];
            float m0 = B[0] * a00;
#pragma unroll
            for (int q = 0; q < 3; q++) m0 += B[1 + q] * z2[q];
            atomicAdd(&out[dst * 32 + o], m0);
#pragma unroll
            for (int p = 0; p < 3; p++) {
                float acc = B[4 + p] * a01;
#pragma unroll
                for (int q = 0; q < 3; q++)
#pragma unroll
                    for (int f = 0; f < 3; f++)
                        acc += B[7 + p * 9 + q * 3 + f] * Z[f * 3 + q];
                atomicAdd(&out[dst * 32 + 8 + o * 3 + p], acc);
            }
        }
    }
}

// ---------------- host orchestration ----------------
extern "C" void kernel_launch(void* const* d_in, const int* in_sizes, int n_in,
                              void* d_out, int out_size) {
    const float* x0       = (const float*)d_in[0];
    const float* x1       = (const float*)d_in[1];
    const float* ef       = (const float*)d_in[2];
    const float* b00      = (const float*)d_in[3];
    const float* b01      = (const float*)d_in[4];
    const float* b10      = (const float*)d_in[5];
    const float* b11      = (const float*)d_in[6];
    const float* kv_w1    = (const float*)d_in[7];
    const float* kv_wnf1  = (const float*)d_in[8];
    const float* kv_w11   = (const float*)d_in[9];
    const float* wq       = (const float*)d_in[10];
    const float* wproj    = (const float*)d_in[11];
    const float* gam      = (const float*)d_in[12];
    const float* bet      = (const float*)d_in[13];
    const float* fc_w1    = (const float*)d_in[14];
    const float* fc_wnf1  = (const float*)d_in[15];
    const float* fc_w11   = (const float*)d_in[16];
    const float* fc_wself = (const float*)d_in[17];
    const int*   esrc     = (const int*)d_in[18];
    const int*   edst     = (const int*)d_in[19];
    float* out = (float*)d_out;

    // CSR by src (rebuilt every launch; globals persist across replays)
    k_csr_zero<<<(NN + 255) / 256, 256>>>();
    k_csr_count<<<EE / 256, 256>>>(esrc);
    k_csr_scan<<<1, 1024>>>();
    k_csr_fill<<<EE / 256, 256>>>(esrc);

    for (int l = 0; l < 2; l++) {
        int use_g = (l != 0);
        k_init<<<(NN * 24 + 255) / 256, 256>>>();
        k_node_pre2<KV><<<NN / 32, 256>>>(x0, x1, use_g,
                                          kv_wnf1 + l * 3 * MID * KV * CC,
                                          kv_w11  + l * MID * KV * CC * 3);
        k_q<<<(NN * 32) / 256, 256>>>(x0, x1, use_g, wq + l * 2 * CC * CKV);
        k_edgeA2<<<NN, 256>>>(ef, kv_w1 + l * 4 * 16 * 16, b00, b01, b10, b11, edst);
        k_edgeB<<<(EE * 4) / 256, 256>>>(edst);
        k_edgeC<<<(EE * 8) / 256, 256>>>(edst);
        k_nodeD<<<NN / 16, 256>>>(x0, x1, use_g, wproj + l * 768, gam + l * 32, bet + l * 32);
    }
    // final fc pass
    k_node_pre2<CO><<<NN / 32, 256>>>(nullptr, nullptr, 1, fc_wnf1, fc_w11);
    k_initout<<<(NN * 32) / 256, 256>>>(fc_wself, out);
    k_edge_fc2<<<NN, 256>>>(ef, fc_w1, b00, b01, b10, b11, edst, out);
}

// round 10
// speedup vs baseline: 2.5122x; 1.1936x over previous
#include <cuda_runtime.h>
#include <math.h>

#define NN 8192
#define EE 131072
#define CC 16
#define MID 16
#define KV 16
#define CKV 8
#define CO 8
#define SCALE 0.35355339059327373f   // 1/sqrt((ckv/HEADS)*4) = 1/sqrt(8)

// ---------------- scratch (static device globals) ----------------
__device__ float g_P0[NN * MID * KV];          // [n][h][o]
__device__ float g_P1[NN * MID * KV];          // [n][h][o]
__device__ float g_P2[NN * MID * 3 * KV];      // [n][h][q][o]
__device__ float g_P3[NN * MID * 9 * KV];      // [n][h][f][q][o]
__device__ float g_q0[NN * CKV];               // [n][d]
__device__ float g_q1[NN * CKV * 3];           // [n][d][m]
__device__ float g_vv[EE * CKV * 4];           // [e][c][(v0,v1x,v1y,v1z)]
__device__ float g_z[EE * 4];                  // [e][head]  (scaled)
__device__ unsigned g_m[NN * 4];               // orderable-uint max per (n,head)
__device__ float g_s[NN * 4];                  // softmax denom
__device__ float g_oo[NN * CKV * 4];           // [n][c][(o0,o1x,o1y,o1z)]
__device__ float g_x0[NN * CC];
__device__ float g_x1[NN * CC * 3];
// CSR by src
__device__ int g_deg[NN];
__device__ int g_cur[NN];
__device__ int g_rs[NN + 1];
__device__ int g_eperm[EE];

__device__ __forceinline__ unsigned f2o(float f) {
    unsigned u = __float_as_uint(f);
    return (u & 0x80000000u) ? ~u : (u | 0x80000000u);
}
__device__ __forceinline__ float o2f(unsigned u) {
    return (u & 0x80000000u) ? __uint_as_float(u ^ 0x80000000u) : __uint_as_float(~u);
}

// ---------------- CSR build ----------------
__global__ void k_csr_zero() {
    int i = blockIdx.x * 256 + threadIdx.x;
    if (i < NN) { g_deg[i] = 0; g_cur[i] = 0; }
}
__global__ void k_csr_count(const int* __restrict__ esrc) {
    int e = blockIdx.x * 256 + threadIdx.x;
    if (e < EE) atomicAdd(&g_deg[esrc[e]], 1);
}
__global__ void k_csr_scan() {     // 1 block, 1024 threads, 8 elems each
    __shared__ int tot[1024];
    int t = threadIdx.x;
    int base = t * 8;
    int loc[8];
    int s = 0;
#pragma unroll
    for (int i = 0; i < 8; i++) { loc[i] = s; s += g_deg[base + i]; }
    tot[t] = s;
    __syncthreads();
    for (int off = 1; off < 1024; off <<= 1) {
        int v = (t >= off) ? tot[t - off] : 0;
        __syncthreads();
        tot[t] += v;
        __syncthreads();
    }
    int excl = (t == 0) ? 0 : tot[t - 1];
#pragma unroll
    for (int i = 0; i < 8; i++) g_rs[base + i] = excl + loc[i];
    if (t == 0) g_rs[NN] = EE;
}
__global__ void k_csr_fill(const int* __restrict__ esrc) {
    int e = blockIdx.x * 256 + threadIdx.x;
    if (e < EE) {
        int s = esrc[e];
        int pos = g_rs[s] + atomicAdd(&g_cur[s], 1);
        g_eperm[pos] = e;
    }
}

// ---------------- init per-layer accumulators ----------------
__global__ void k_init() {
    int i = blockIdx.x * blockDim.x + threadIdx.x;   // covers NN*32
    if (i < NN * 4) { g_m[i] = 0x007fffffu; g_s[i] = 0.f; }
    if (i < NN * 32) g_oo[i] = 0.f;
}

// ---------------- node precompute v3: thread owns output row j, W in regs ----------------
// grid: (NN/128, JT/256), block 256. Unified j over [0, 224*KVD):
//  [0,16K): P0 (x0)  [16K,32K): P1 (x0)  [32K,80K): P2 (x1,q)  [80K,224K): P3 (x1,q)
template<int KVD>
__global__ void k_node_pre3(const float* __restrict__ xin0, const float* __restrict__ xin1,
                            int use_g,
                            const float* __restrict__ wnf1, const float* __restrict__ w11) {
    __shared__ float sx[4][128][16];    // [q (3=scalar x0)][node][i]
    const float* x0 = use_g ? g_x0 : xin0;
    const float* x1 = use_g ? g_x1 : xin1;
    int nb = blockIdx.x * 128;
    int t = threadIdx.x;
    for (int idx = t; idx < 128 * 16; idx += 256) sx[3][idx >> 4][idx & 15] = x0[nb * 16 + idx];
    for (int idx = t; idx < 128 * 48; idx += 256) {
        int nl = idx / 48, r = idx % 48;
        sx[r % 3][nl][r / 3] = x1[nb * 48 + idx];
    }

    const int slice = 16 * KVD * 16;
    int j = blockIdx.y * 256 + t;

    int q;
    const float* wrow;
    int wstride;           // element stride between consecutive i in the weight row
    float* gptr;
    int gstride;
    if (j < 32 * KVD) {
        q = 3; wrow = wnf1 + j * 16; wstride = 1;
        if (j < 16 * KVD) { gptr = g_P0 + j; }
        else              { gptr = g_P1 + (j - 16 * KVD); }
        gstride = 16 * KVD;
    } else if (j < 80 * KVD) {
        int r = j - 32 * KVD;
        int h = r / (3 * KVD);
        int o = r % KVD;
        q = (r / KVD) % 3;
        wrow = wnf1 + 2 * slice + (h * KVD + o) * 16; wstride = 1;
        gptr = g_P2 + r; gstride = 48 * KVD;
    } else {
        int r = j - 80 * KVD;
        int h = r / (9 * KVD);
        int f = (r / (3 * KVD)) % 3;
        int o = r % KVD;
        q = (r / KVD) % 3;
        wrow = w11 + (h * KVD + o) * 16 * 3 + f; wstride = 3;
        gptr = g_P3 + r; gstride = 144 * KVD;
    }
    float w[16];
#pragma unroll
    for (int i = 0; i < 16; i++) w[i] = wrow[i * wstride];

    __syncthreads();
    const float* xq = &sx[q][0][0];
#pragma unroll 4
    for (int nl = 0; nl < 128; nl++) {
        const float4* xv = (const float4*)(xq + nl * 16);
        float4 xa = xv[0], xb = xv[1], xc = xv[2], xd = xv[3];
        float a = w[0] * xa.x + w[1] * xa.y + w[2] * xa.z + w[3] * xa.w
                + w[4] * xb.x + w[5] * xb.y + w[6] * xb.z + w[7] * xb.w
                + w[8] * xc.x + w[9] * xc.y + w[10] * xc.z + w[11] * xc.w
                + w[12] * xd.x + w[13] * xd.y + w[14] * xd.z + w[15] * xd.w;
        gptr[(nb + nl) * gstride] = a;
    }
}

// ---------------- q vectors ----------------
__global__ void k_q(const float* __restrict__ xin0, const float* __restrict__ xin1,
                    int use_g, const float* __restrict__ wql) {
    const float* x0 = use_g ? g_x0 : xin0;
    const float* x1 = use_g ? g_x1 : xin1;
    int i = blockIdx.x * 256 + threadIdx.x;   // NN*32
    if (i >= NN * 32) return;
    int n = i >> 5, j = i & 31;
    if (j < 8) {
        float a = 0.f;
#pragma unroll
        for (int c = 0; c < 16; c++) a += x0[n * 16 + c] * wql[c * 8 + j];
        g_q0[n * 8 + j] = a;
    } else {
        int r = j - 8; int d = r / 3, m = r % 3;
        float a = 0.f;
#pragma unroll
        for (int c = 0; c < 16; c++) a += x1[n * 48 + c * 3 + m] * wql[128 + c * 8 + d];
        g_q1[n * 24 + r] = a;
    }
}

// ---------------- edge pass A (CSR): block per src node, P in SMEM ----------------
// 256 threads = 16 edges x 16 threads(o) per chunk
__global__ void k_edgeA2(const float* __restrict__ ef, const float* __restrict__ w1l,
                         const float* __restrict__ b00, const float* __restrict__ b01,
                         const float* __restrict__ b10, const float* __restrict__ b11,
                         const int* __restrict__ edst) {
    __shared__ float sP0[256], sP1[256], sP2[768], sP3[2304];
    __shared__ float sw1[1024];
    __shared__ float sH[16][64];
    __shared__ float sef[16][16];
    __shared__ float sB[16][34];
    __shared__ float sq[16][32];
    __shared__ int se[16], sdst[16];
    int n = blockIdx.x;
    int start = g_rs[n], end = g_rs[n + 1];
    if (start == end) return;
    int t = threadIdx.x;
    sP0[t] = g_P0[n * 256 + t];
    sP1[t] = g_P1[n * 256 + t];
    for (int i = t; i < 768; i += 256) sP2[i] = g_P2[n * 768 + i];
    for (int i = t; i < 2304; i += 256) sP3[i] = g_P3[n * 2304 + i];
    for (int i = t; i < 1024; i += 256) sw1[i] = w1l[i];

    for (int c = start; c < end; c += 16) {
        int ne = min(16, end - c);
        __syncthreads();                          // smem reuse fence (also orders sP/sw1 loads)
        if (t < 16) {
            int e = (t < ne) ? g_eperm[c + t] : g_eperm[c];
            se[t] = e;
            sdst[t] = edst[e];
        }
        __syncthreads();
        { int le = t >> 4, f = t & 15; if (le < ne) sef[le][f] = ef[se[le] * 16 + f]; }
        for (int idx = t; idx < 16 * 34; idx += 256) {
            int le = idx / 34, j = idx % 34;
            if (le < ne) {
                int e = se[le];
                float v;
                if (j == 0)      v = b00[e];
                else if (j < 4)  v = b10[e * 3 + j - 1];
                else if (j < 7)  v = b01[e * 3 + j - 4];
                else             v = b11[e * 27 + j - 7];
                sB[le][j] = v;
            }
        }
        for (int idx = t; idx < 16 * 32; idx += 256) {
            int le = idx >> 5, j = idx & 31;
            if (le < ne) {
                int dst = sdst[le];
                sq[le][j] = (j < 8) ? g_q0[dst * 8 + j] : g_q1[dst * 24 + (j - 8)];
            }
        }
        __syncthreads();
#pragma unroll
        for (int k = 0; k < 4; k++) {
            int idx = t + k * 256;
            int le = idx >> 6, ph = idx & 63, p = ph >> 4, h = ph & 15;
            if (le < ne) {
                float a = 0.f;
#pragma unroll
                for (int f = 0; f < 16; f++) a += sef[le][f] * sw1[p * 256 + f * 16 + h];
                sH[le][ph] = fmaxf(a, 0.f);
            }
        }
        __syncthreads();
        // message compute (unguarded reads from smem; stores guarded)
        int le = t >> 4, o = t & 15;
        const float* H = sH[le];
        float a00 = 0.f, a01 = 0.f;
        float z2[3] = {0.f, 0.f, 0.f};
        float Z[9] = {0.f, 0.f, 0.f, 0.f, 0.f, 0.f, 0.f, 0.f, 0.f};
#pragma unroll
        for (int h = 0; h < 16; h++) {
            float h0 = H[h], h1 = H[16 + h], h2 = H[32 + h], h3 = H[48 + h];
            a00 += h0 * sP0[h * 16 + o];
            a01 += h1 * sP1[h * 16 + o];
#pragma unroll
            for (int q = 0; q < 3; q++) z2[q] += h2 * sP2[h * 48 + q * 16 + o];
#pragma unroll
            for (int fq = 0; fq < 9; fq++) Z[fq] += h3 * sP3[h * 144 + fq * 16 + o];
        }
        const float* B = sB[le];
        float kv0 = B[0] * a00;
#pragma unroll
        for (int q = 0; q < 3; q++) kv0 += B[1 + q] * z2[q];
        float kv1[3];
#pragma unroll
        for (int p = 0; p < 3; p++) {
            float acc = B[4 + p] * a01;
#pragma unroll
            for (int q = 0; q < 3; q++)
#pragma unroll
                for (int f = 0; f < 3; f++)
                    acc += B[7 + p * 9 + q * 3 + f] * Z[f * 3 + q];
            kv1[p] = acc;
        }
        float zpart = 0.f;
        if (o < 8) {
            zpart = sq[le][o] * kv0;
#pragma unroll
            for (int p = 0; p < 3; p++) zpart += sq[le][8 + o * 3 + p] * kv1[p];
        }
        float zsum = zpart + __shfl_xor_sync(0xffffffffu, zpart, 1);
        if (le < ne) {
            int e = se[le], dst = sdst[le];
            if (o < 8 && (o & 1) == 0) {
                int head = o >> 1;
                float zs = zsum * SCALE;
                g_z[e * 4 + head] = zs;
                atomicMax(&g_m[dst * 4 + head], f2o(zs));
            }
            if (o >= 8) {
                int cc = o - 8;
                float4 v4 = make_float4(kv0, kv1[0], kv1[1], kv1[2]);
                ((float4*)g_vv)[e * 8 + cc] = v4;
            }
        }
    }
}

// ---------------- edge pass B: exp-sum ----------------
__global__ void k_edgeB(const int* __restrict__ edst) {
    int i = blockIdx.x * 256 + threadIdx.x;   // E*4
    if (i >= EE * 4) return;
    int e = i >> 2, head = i & 3;
    int dst = edst[e];
    float m = o2f(g_m[dst * 4 + head]);
    float ez = __expf(g_z[i] - m);
    atomicAdd(&g_s[dst * 4 + head], ez);
}

// ---------------- edge pass C: alpha * v scatter (float4 values) ----------------
__global__ void k_edgeC(const int* __restrict__ edst) {
    int i = blockIdx.x * 256 + threadIdx.x;   // E*8
    if (i >= EE * 8) return;
    int e = i >> 3, c = i & 7, head = c >> 1;
    int dst = edst[e];
    float m = o2f(g_m[dst * 4 + head]);
    float s = g_s[dst * 4 + head];
    float alpha = __expf(g_z[e * 4 + head] - m) / (s + 1e-9f);
    float4 v = ((const float4*)g_vv)[i];
    float* op = g_oo + (dst * 8 + c) * 4;
    atomicAdd(op + 0, alpha * v.x);
    atomicAdd(op + 1, alpha * v.y);
    atomicAdd(op + 2, alpha * v.z);
    atomicAdd(op + 3, alpha * v.w);
}

// ---------------- node pass D: projection + SE3 norm ----------------
__global__ void k_nodeD(const float* __restrict__ xin0, const float* __restrict__ xin1,
                        int use_g,
                        const float* __restrict__ wp, const float* __restrict__ gamma,
                        const float* __restrict__ beta) {
    __shared__ float s0[16][24];
    __shared__ float s1[16][72];
    const float* x0 = use_g ? g_x0 : xin0;
    const float* x1 = use_g ? g_x1 : xin1;
    int n0b = blockIdx.x * 16;
    int t = threadIdx.x;
    for (int idx = t; idx < 16 * 24; idx += 256) {
        int nl = idx / 24, c = idx % 24; int n = n0b + nl;
        s0[nl][c] = (c < 8) ? g_oo[(n * 8 + c) * 4] : x0[n * 16 + (c - 8)];
    }
    for (int idx = t; idx < 16 * 72; idx += 256) {
        int nl = idx / 72, r = idx % 72; int c = r / 3, m = r % 3; int n = n0b + nl;
        s1[nl][r] = (c < 8) ? g_oo[(n * 8 + c) * 4 + 1 + m] : x1[n * 48 + (c - 8) * 3 + m];
    }
    __syncthreads();

    int nl = t / 16, d = t % 16; int n = n0b + nl;
    float y0 = 0.f, y1[3] = {0.f, 0.f, 0.f};
#pragma unroll
    for (int c = 0; c < 24; c++) {
        y0 += s0[nl][c] * wp[c * 16 + d];
        float w = wp[384 + c * 16 + d];
        y1[0] += s1[nl][c * 3 + 0] * w;
        y1[1] += s1[nl][c * 3 + 1] * w;
        y1[2] += s1[nl][c * 3 + 2] * w;
    }
    {
        float nv = sqrtf(y0 * y0 + 1e-12f);
        float r = nv;
#pragma unroll
        for (int mk = 1; mk < 16; mk <<= 1) r += __shfl_xor_sync(0xffffffffu, r, mk);
        float mu = r * (1.f / 16.f);
        float dv = nv - mu;
        float v = dv * dv;
#pragma unroll
        for (int mk = 1; mk < 16; mk <<= 1) v += __shfl_xor_sync(0xffffffffu, v, mk);
        v *= (1.f / 16.f);
        float ln = dv * rsqrtf(v + 1e-5f) * gamma[d] + beta[d];
        float fac = fmaxf(ln, 0.f) / (nv + 1e-3f);
        g_x0[n * 16 + d] = y0 * fac;
    }
    {
        float nv = sqrtf(y1[0] * y1[0] + y1[1] * y1[1] + y1[2] * y1[2] + 1e-12f);
        float r = nv;
#pragma unroll
        for (int mk = 1; mk < 16; mk <<= 1) r += __shfl_xor_sync(0xffffffffu, r, mk);
        float mu = r * (1.f / 16.f);
        float dv = nv - mu;
        float v = dv * dv;
#pragma unroll
        for (int mk = 1; mk < 16; mk <<= 1) v += __shfl_xor_sync(0xffffffffu, v, mk);
        v *= (1.f / 16.f);
        float ln = dv * rsqrtf(v + 1e-5f) * gamma[16 + d] + beta[16 + d];
        float fac = fmaxf(ln, 0.f) / (nv + 1e-3f);
        g_x1[n * 48 + d * 3 + 0] = y1[0] * fac;
        g_x1[n * 48 + d * 3 + 1] = y1[1] * fac;
        g_x1[n * 48 + d * 3 + 2] = y1[2] * fac;
    }
}

// ---------------- final: init output with self term ----------------
__global__ void k_initout(const float* __restrict__ wself, float* __restrict__ out) {
    int i = blockIdx.x * 256 + threadIdx.x;   // N*32
    if (i >= NN * 32) return;
    int n = i >> 5, j = i & 31;
    float a = 0.f;
    if (j < 8) {
#pragma unroll
        for (int c = 0; c < 16; c++) a += g_x0[n * 16 + c] * wself[c * 8 + j];
    } else {
        int r = j - 8; int o = r / 3, m = r % 3;
#pragma unroll
        for (int c = 0; c < 16; c++) a += g_x1[n * 48 + c * 3 + m] * wself[128 + c * 8 + o];
    }
    out[i] = a;
}

// ---------------- final fc pass (CSR): 32 edges x 8 threads(o) ----------------
__global__ void k_edge_fc2(const float* __restrict__ ef, const float* __restrict__ w1l,
                           const float* __restrict__ b00, const float* __restrict__ b01,
                           const float* __restrict__ b10, const float* __restrict__ b11,
                           const int* __restrict__ edst, float* __restrict__ out) {
    __shared__ float sP0[128], sP1[128], sP2[384], sP3[1152];
    __shared__ float sw1[1024];
    __shared__ float sH[32][64];
    __shared__ float sef[32][16];
    __shared__ float sB[32][34];
    __shared__ int se[32], sdst[32];
    int n = blockIdx.x;
    int start = g_rs[n], end = g_rs[n + 1];
    if (start == end) return;
    int t = threadIdx.x;
    if (t < 128) { sP0[t] = g_P0[n * 128 + t]; sP1[t] = g_P1[n * 128 + t]; }
    for (int i = t; i < 384; i += 256) sP2[i] = g_P2[n * 384 + i];
    for (int i = t; i < 1152; i += 256) sP3[i] = g_P3[n * 1152 + i];
    for (int i = t; i < 1024; i += 256) sw1[i] = w1l[i];

    for (int c = start; c < end; c += 32) {
        int ne = min(32, end - c);
        __syncthreads();
        if (t < 32) {
            int e = (t < ne) ? g_eperm[c + t] : g_eperm[c];
            se[t] = e;
            sdst[t] = edst[e];
        }
        __syncthreads();
        for (int idx = t; idx < 32 * 16; idx += 256) {
            int le = idx >> 4, f = idx & 15;
            if (le < ne) sef[le][f] = ef[se[le] * 16 + f];
        }
        for (int idx = t; idx < 32 * 34; idx += 256) {
            int le = idx / 34, j = idx % 34;
            if (le < ne) {
                int e = se[le];
                float v;
                if (j == 0)      v = b00[e];
                else if (j < 4)  v = b10[e * 3 + j - 1];
                else if (j < 7)  v = b01[e * 3 + j - 4];
                else             v = b11[e * 27 + j - 7];
                sB[le][j] = v;
            }
        }
        __syncthreads();
#pragma unroll
        for (int k = 0; k < 8; k++) {
            int idx = t + k * 256;
            int le = idx >> 6, ph = idx & 63, p = ph >> 4, h = ph & 15;
            if (le < ne) {
                float a = 0.f;
#pragma unroll
                for (int f = 0; f < 16; f++) a += sef[le][f] * sw1[p * 256 + f * 16 + h];
                sH[le][ph] = fmaxf(a, 0.f);
            }
        }
        __syncthreads();
        int le = t >> 3, o = t & 7;
        if (le < ne) {
            const float* H = sH[le];
            float a00 = 0.f, a01 = 0.f;
            float z2[3] = {0.f, 0.f, 0.f};
            float Z[9] = {0.f, 0.f, 0.f, 0.f, 0.f, 0.f, 0.f, 0.f, 0.f};
#pragma unroll
            for (int h = 0; h < 16; h++) {
                float h0 = H[h], h1 = H[16 + h], h2 = H[32 + h], h3 = H[48 + h];
                a00 += h0 * sP0[h * 8 + o];
                a01 += h1 * sP1[h * 8 + o];
#pragma unroll
                for (int q = 0; q < 3; q++) z2[q] += h2 * sP2[h * 24 + q * 8 + o];
#pragma unroll
                for (int fq = 0; fq < 9; fq++) Z[fq] += h3 * sP3[h * 72 + fq * 8 + o];
            }
            const float* B = sB[le];
            int dst = sdst[le];
            float m0 = B[0] * a00;
#pragma unroll
            for (int q = 0; q < 3; q++) m0 += B[1 + q] * z2[q];
            atomicAdd(&out[dst * 32 + o], m0);
#pragma unroll
            for (int p = 0; p < 3; p++) {
                float acc = B[4 + p] * a01;
#pragma unroll
                for (int q = 0; q < 3; q++)
#pragma unroll
                    for (int f = 0; f < 3; f++)
                        acc += B[7 + p * 9 + q * 3 + f] * Z[f * 3 + q];
                atomicAdd(&out[dst * 32 + 8 + o * 3 + p], acc);
            }
        }
    }
}

// ---------------- host orchestration ----------------
extern "C" void kernel_launch(void* const* d_in, const int* in_sizes, int n_in,
                              void* d_out, int out_size) {
    const float* x0       = (const float*)d_in[0];
    const float* x1       = (const float*)d_in[1];
    const float* ef       = (const float*)d_in[2];
    const float* b00      = (const float*)d_in[3];
    const float* b01      = (const float*)d_in[4];
    const float* b10      = (const float*)d_in[5];
    const float* b11      = (const float*)d_in[6];
    const float* kv_w1    = (const float*)d_in[7];
    const float* kv_wnf1  = (const float*)d_in[8];
    const float* kv_w11   = (const float*)d_in[9];
    const float* wq       = (const float*)d_in[10];
    const float* wproj    = (const float*)d_in[11];
    const float* gam      = (const float*)d_in[12];
    const float* bet      = (const float*)d_in[13];
    const float* fc_w1    = (const float*)d_in[14];
    const float* fc_wnf1  = (const float*)d_in[15];
    const float* fc_w11   = (const float*)d_in[16];
    const float* fc_wself = (const float*)d_in[17];
    const int*   esrc     = (const int*)d_in[18];
    const int*   edst     = (const int*)d_in[19];
    float* out = (float*)d_out;

    // CSR by src
    k_csr_zero<<<(NN + 255) / 256, 256>>>();
    k_csr_count<<<EE / 256, 256>>>(esrc);
    k_csr_scan<<<1, 1024>>>();
    k_csr_fill<<<EE / 256, 256>>>(esrc);

    for (int l = 0; l < 2; l++) {
        int use_g = (l != 0);
        k_init<<<(NN * 32) / 256, 256>>>();
        k_node_pre3<KV><<<dim3(NN / 128, (224 * KV) / 256), 256>>>(
            x0, x1, use_g,
            kv_wnf1 + l * 3 * MID * KV * CC,
            kv_w11  + l * MID * KV * CC * 3);
        k_q<<<(NN * 32) / 256, 256>>>(x0, x1, use_g, wq + l * 2 * CC * CKV);
        k_edgeA2<<<NN, 256>>>(ef, kv_w1 + l * 4 * 16 * 16, b00, b01, b10, b11, edst);
        k_edgeB<<<(EE * 4) / 256, 256>>>(edst);
        k_edgeC<<<(EE * 8) / 256, 256>>>(edst);
        k_nodeD<<<NN / 16, 256>>>(x0, x1, use_g, wproj + l * 768, gam + l * 32, bet + l * 32);
    }
    // final fc pass
    k_node_pre3<CO><<<dim3(NN / 128, (224 * CO) / 256), 256>>>(nullptr, nullptr, 1, fc_wnf1, fc_w11);
    k_initout<<<(NN * 32) / 256, 256>>>(fc_wself, out);
    k_edge_fc2<<<NN, 256>>>(ef, fc_w1, b00, b01, b10, b11, edst, out);
}